// round 3
// baseline (speedup 1.0000x reference)
#include <cuda_runtime.h>
#include <math.h>

#define NB 4
#define NH 480
#define NW 640
#define NSEM 16
#define NC 20
#define MM 480
#define VRD 100
#define NZV 80
#define BANDLO 13
#define BANDN 12

// Scratch (device globals; no allocations allowed)
__device__ __align__(16) float g_vox0[NB][VRD][VRD][NZV];           // occupancy ch
__device__ __align__(16) float g_voxC[NB][VRD][VRD][BANDN][NSEM];   // sem chans, z-band only
__device__ __align__(16) float g_compact2[NB][VRD * VRD][20];       // packed: ch0,ch1,sem0..15,pad,pad
__device__ float g_pose[NB][4];                                     // cos_t, sin_t, tx, ty

__device__ __forceinline__ void red_add_v4(float* p, float a, float b, float c, float d) {
    asm volatile("red.global.add.v4.f32 [%0], {%1, %2, %3, %4};"
                 :: "l"(p), "f"(a), "f"(b), "f"(c), "f"(d) : "memory");
}
__device__ __forceinline__ void red_add_v2(float* p, float a, float b) {
    asm volatile("red.global.add.v2.f32 [%0], {%1, %2};"
                 :: "l"(p), "f"(a), "f"(b) : "memory");
}

// ---------------------------------------------------------------------------
// zero voxel scratch + (block 0) pose math
__global__ void zero_pose_kernel(const float* __restrict__ pose_obs,
                                 const float* __restrict__ poses_last,
                                 float* __restrict__ poses_out) {
    if (blockIdx.x == 0 && threadIdx.x < NB) {
        int b = threadIdx.x;
        const float R2D = 57.29577951308232f;
        float plx = poses_last[3 * b + 0];
        float ply = poses_last[3 * b + 1];
        float plo = poses_last[3 * b + 2];
        float dx = pose_obs[3 * b + 0];
        float dy = pose_obs[3 * b + 1];
        float dth = pose_obs[3 * b + 2];
        float r = __fdiv_rn(plo, R2D);
        float sr = sinf(r), cr = cosf(r);
        float yy = __fadd_rn(__fadd_rn(ply, __fmul_rn(dx, sr)), __fmul_rn(dy, cr));
        float xx = __fsub_rn(__fadd_rn(plx, __fmul_rn(dx, cr)), __fmul_rn(dy, sr));
        float oo = __fadd_rn(plo, __fmul_rn(dth, R2D));
        oo = __fadd_rn(fmodf(__fsub_rn(oo, 180.0f), 360.0f), 180.0f);
        oo = __fsub_rn(fmodf(__fadd_rn(oo, 180.0f), 360.0f), 180.0f);
        poses_out[3 * b + 0] = xx;
        poses_out[3 * b + 1] = yy;
        poses_out[3 * b + 2] = oo;
        float stx = __fdiv_rn(-__fsub_rn(__fdiv_rn(__fmul_rn(xx, 100.0f), 5.0f), 240.0f), 240.0f);
        float sty = __fdiv_rn(-__fsub_rn(__fdiv_rn(__fmul_rn(yy, 100.0f), 5.0f), 240.0f), 240.0f);
        float tt = __fdiv_rn(__fmul_rn(__fsub_rn(90.0f, oo), 3.14159265358979323846f), 180.0f);
        g_pose[b][0] = cosf(tt);
        g_pose[b][1] = sinf(tt);
        g_pose[b][2] = stx;
        g_pose[b][3] = sty;
    }
    const int na = NB * VRD * VRD * NZV / 4;
    const int nb = NB * VRD * VRD * BANDN * NSEM / 4;
    float4* a = reinterpret_cast<float4*>(&g_vox0[0][0][0][0]);
    float4* c = reinterpret_cast<float4*>(&g_voxC[0][0][0][0][0]);
    float4 z = make_float4(0.f, 0.f, 0.f, 0.f);
    int stride = gridDim.x * blockDim.x;
    for (int i = blockIdx.x * blockDim.x + threadIdx.x; i < na; i += stride) a[i] = z;
    for (int i = blockIdx.x * blockDim.x + threadIdx.x; i < nb; i += stride) c[i] = z;
}

// ---------------------------------------------------------------------------
__global__ void splat_kernel(const float* __restrict__ obs, float focal) {
    int idx = blockIdx.x * blockDim.x + threadIdx.x;
    if (idx >= NB * NH * NW) return;
    int w = idx % NW;
    int t = idx / NW;
    int h = t % NH;
    int b = t / NH;

    size_t obs_b = (size_t)b * NC * NH * NW;
    size_t pix = (size_t)h * NW + w;
    float depth = __ldcs(obs + obs_b + (size_t)3 * NH * NW + pix);

    float X = __fdiv_rn(__fmul_rn(__fsub_rn((float)w, 319.5f), depth), focal);
    float Z = __fdiv_rn(__fmul_rn(__fsub_rn((float)(NH - 1 - h), 239.5f), depth), focal);

    float t0 = __fdiv_rn(__fadd_rn(X, 250.0f), 5.0f);
    t0 = __fmul_rn(__fdiv_rn(__fsub_rn(t0, 50.0f), 100.0f), 2.0f);
    float pos0 = __fadd_rn(__fmul_rn(t0, 50.0f), 50.0f);
    float t1 = __fdiv_rn(depth, 5.0f);
    t1 = __fmul_rn(__fdiv_rn(__fsub_rn(t1, 50.0f), 100.0f), 2.0f);
    float pos1 = __fadd_rn(__fmul_rn(t1, 50.0f), 50.0f);
    float t2 = __fdiv_rn(__fadd_rn(Z, 88.0f), 5.0f);
    t2 = __fmul_rn(__fdiv_rn(__fsub_rn(t2, 32.0f), 80.0f), 2.0f);
    float pos2 = __fadd_rn(__fmul_rn(t2, 40.0f), 40.0f);

    float f0 = floorf(pos0), f1 = floorf(pos1), f2 = floorf(pos2);
    float wg0[2], wg1[2], wg2[2];
    int i0[2], i1[2], i2[2];
#pragma unroll
    for (int o = 0; o < 2; o++) {
        float p = f0 + (float)o;
        bool s = (p > 0.0f) && (p < 100.0f);
        wg0[o] = s ? (1.0f - fabsf(__fsub_rn(pos0, p))) : 0.0f;
        i0[o] = s ? (int)p : 0;
        p = f1 + (float)o;
        s = (p > 0.0f) && (p < 100.0f);
        wg1[o] = s ? (1.0f - fabsf(__fsub_rn(pos1, p))) : 0.0f;
        i1[o] = s ? (int)p : 0;
        p = f2 + (float)o;
        s = (p > 0.0f) && (p < 80.0f);
        wg2[o] = s ? (1.0f - fabsf(__fsub_rn(pos2, p))) : 0.0f;
        i2[o] = s ? (int)p : 0;
    }
    if ((wg0[0] == 0.f && wg0[1] == 0.f) ||
        (wg1[0] == 0.f && wg1[1] == 0.f) ||
        (wg2[0] == 0.f && wg2[1] == 0.f))
        return;

    bool band = ((wg2[0] > 0.f && i2[0] >= BANDLO && i2[0] < BANDLO + BANDN) ||
                 (wg2[1] > 0.f && i2[1] >= BANDLO && i2[1] < BANDLO + BANDN));
    float sem[NSEM];
    if (band) {
#pragma unroll
        for (int s = 0; s < NSEM; s++)
            sem[s] = __ldcs(obs + obs_b + (size_t)(4 + s) * NH * NW + pix);
    }

    bool zpair = (wg2[0] > 0.f) && (wg2[1] > 0.f);
    bool zalign = zpair && ((i2[0] & 1) == 0);

#pragma unroll
    for (int a = 0; a < 2; a++) {
        if (wg0[a] == 0.f) continue;
#pragma unroll
        for (int c = 0; c < 2; c++) {
            float wac = __fmul_rn(wg0[a], wg1[c]);
            if (wac == 0.f) continue;

            float wz0 = __fmul_rn(wac, wg2[0]);
            float wz1 = __fmul_rn(wac, wg2[1]);
            float* v0base = &g_vox0[b][i1[c]][i0[a]][0];
            if (zalign) {
                red_add_v2(v0base + i2[0], wz0, wz1);
            } else {
                if (wg2[0] > 0.f) atomicAdd(v0base + i2[0], wz0);
                if (wg2[1] > 0.f) atomicAdd(v0base + i2[1], wz1);
            }

#pragma unroll
            for (int e = 0; e < 2; e++) {
                float wt = (e == 0) ? wz0 : wz1;
                if (wt == 0.f) continue;
                int zb = i2[e] - BANDLO;
                if ((unsigned)zb < (unsigned)BANDN) {
                    float* dst = &g_voxC[b][i1[c]][i0[a]][zb][0];
#pragma unroll
                    for (int q = 0; q < 4; q++)
                        red_add_v4(dst + q * 4,
                                   __fmul_rn(sem[q * 4 + 0], wt),
                                   __fmul_rn(sem[q * 4 + 1], wt),
                                   __fmul_rn(sem[q * 4 + 2], wt),
                                   __fmul_rn(sem[q * 4 + 3], wt));
                }
            }
        }
    }
}

// ---------------------------------------------------------------------------
__global__ void proj_kernel(float* __restrict__ fp_out) {
    int tid = blockIdx.x * blockDim.x + threadIdx.x;
    int cell = tid >> 2;
    int lane = tid & 3;
    if (cell >= NB * VRD * VRD) return;
    int p0 = cell % VRD;
    int t = cell / VRD;
    int p1 = t % VRD;
    int b = t / VRD;

    const float4* v0 = reinterpret_cast<const float4*>(&g_vox0[b][p1][p0][0]);
    float s_all = 0.f, s_band = 0.f;
#pragma unroll
    for (int q0 = 0; q0 < NZV / 16; q0++) {
        int q = q0 * 4 + lane;
        float4 v = __ldcs(v0 + q);
        float r0 = rintf(v.x), r1 = rintf(v.y), r2 = rintf(v.z), r3 = rintf(v.w);
        s_all += r0 + r1 + r2 + r3;
        int z = q * 4;
        if (z + 0 >= BANDLO && z + 0 < BANDLO + BANDN) s_band += r0;
        if (z + 1 >= BANDLO && z + 1 < BANDLO + BANDN) s_band += r1;
        if (z + 2 >= BANDLO && z + 2 < BANDLO + BANDN) s_band += r2;
        if (z + 3 >= BANDLO && z + 3 < BANDLO + BANDN) s_band += r3;
    }

    float ssem[NSEM];
#pragma unroll
    for (int s = 0; s < NSEM; s++) ssem[s] = 0.f;
    const float4* vc = reinterpret_cast<const float4*>(&g_voxC[b][p1][p0][0][0]);
#pragma unroll
    for (int zb0 = 0; zb0 < BANDN / 4; zb0++) {
        int zb = zb0 * 4 + lane;
#pragma unroll
        for (int q = 0; q < NSEM / 4; q++) {
            float4 v = __ldcs(vc + zb * (NSEM / 4) + q);
            ssem[q * 4 + 0] += rintf(v.x);
            ssem[q * 4 + 1] += rintf(v.y);
            ssem[q * 4 + 2] += rintf(v.z);
            ssem[q * 4 + 3] += rintf(v.w);
        }
    }

#pragma unroll
    for (int off = 1; off < 4; off <<= 1) {
        s_all += __shfl_xor_sync(0xffffffffu, s_all, off);
        s_band += __shfl_xor_sync(0xffffffffu, s_band, off);
#pragma unroll
        for (int s = 0; s < NSEM; s++)
            ssem[s] += __shfl_xor_sync(0xffffffffu, ssem[s], off);
    }

    if (lane == 0) {
        int sp = p1 * VRD + p0;
        float* row = &g_compact2[b][sp][0];
        float m = fminf(fmaxf(__fdiv_rn(s_band, 1.0f), 0.f), 1.f);
        row[0] = m;
        row[1] = fminf(fmaxf(__fdiv_rn(s_all, 1.0f), 0.f), 1.f);
        fp_out[(size_t)b * VRD * VRD + sp] = m;
#pragma unroll
        for (int s = 0; s < NSEM; s++)
            row[2 + s] = fminf(fmaxf(__fdiv_rn(ssem[s], 5.0f), 0.f), 1.f);
    }
}

// ---------------------------------------------------------------------------
__device__ __forceinline__ void xform_pixel(int b, int h, int w,
                                            const float* __restrict__ maps_last,
                                            float* __restrict__ map_out,
                                            float ct, float sn, float tx, float ty) {
    const float step = 2.0f / 479.0f;
    float gx = __fsub_rn(__fmul_rn((float)w, step), 1.0f);
    float gy = __fsub_rn(__fmul_rn((float)h, step), 1.0f);
    float x = __fmul_rn(__fmul_rn(__fadd_rn(__fadd_rn(gx, tx), 1.0f), 0.5f), 479.0f);
    float y = __fmul_rn(__fmul_rn(__fadd_rn(__fadd_rn(gy, ty), 1.0f), 0.5f), 479.0f);
    float x0 = floorf(x), y0 = floorf(y);
    float wxv[2] = { __fsub_rn(__fadd_rn(x0, 1.0f), x), __fsub_rn(x, x0) };
    float wyv[2] = { __fsub_rn(__fadd_rn(y0, 1.0f), y), __fsub_rn(y, y0) };

    float pw[16];
    int po[16];
    bool any = false;
#pragma unroll
    for (int i = 0; i < 2; i++) {
        float qxf = x0 + (float)i;
#pragma unroll
        for (int j = 0; j < 2; j++) {
            float qyf = y0 + (float)j;
            float wk = __fmul_rn(wxv[i], wyv[j]);
            int base = (i * 2 + j) * 4;
            bool v = (qxf >= 0.f) && (qxf <= 479.f) && (qyf >= 0.f) && (qyf <= 479.f) && (wk > 0.f);
            float rx0 = 0.f, ry0 = 0.f;
            float wrx[2] = {0.f, 0.f}, wry[2] = {0.f, 0.f};
            if (v) {
                float gqx = __fsub_rn(__fmul_rn(qxf, step), 1.0f);
                float gqy = __fsub_rn(__fmul_rn(qyf, step), 1.0f);
                float r0 = __fsub_rn(__fmul_rn(gqx, ct), __fmul_rn(gqy, sn));
                float r1 = __fadd_rn(__fmul_rn(gqx, sn), __fmul_rn(gqy, ct));
                float rx = __fmul_rn(__fmul_rn(__fadd_rn(r0, 1.0f), 0.5f), 479.0f);
                float ry = __fmul_rn(__fmul_rn(__fadd_rn(r1, 1.0f), 0.5f), 479.0f);
                rx0 = floorf(rx);
                ry0 = floorf(ry);
                wrx[0] = __fsub_rn(__fadd_rn(rx0, 1.0f), rx);
                wrx[1] = __fsub_rn(rx, rx0);
                wry[0] = __fsub_rn(__fadd_rn(ry0, 1.0f), ry);
                wry[1] = __fsub_rn(ry, ry0);
            }
#pragma unroll
            for (int di = 0; di < 2; di++) {
#pragma unroll
                for (int dj = 0; dj < 2; dj++) {
                    float fx = rx0 + (float)di;
                    float fy = ry0 + (float)dj;
                    bool inr = v && (fx >= 190.f) && (fx <= 289.f) && (fy >= 240.f) && (fy <= 339.f);
                    float wgt = inr ? __fmul_rn(wk, __fmul_rn(wrx[di], wry[dj])) : 0.f;
                    int off = inr ? (((int)fy - 240) * VRD + ((int)fx - 190)) : 0;
                    int slot = base + di * 2 + dj;
                    pw[slot] = wgt;
                    po[slot] = off;
                    any = any || (wgt != 0.f);
                }
            }
        }
    }

    size_t plane = (size_t)MM * MM;
    size_t pixoff = (size_t)b * NC * plane + (size_t)h * MM + w;
    if (!any) {
#pragma unroll
        for (int c = 0; c < NC; c++)
            __stcs(map_out + pixoff + (size_t)c * plane,
                   fmaxf(__ldcs(maps_last + pixoff + (size_t)c * plane), 0.0f));
        return;
    }
    __stcs(map_out + pixoff + 2 * plane, fmaxf(__ldcs(maps_last + pixoff + 2 * plane), 0.0f));
    __stcs(map_out + pixoff + 3 * plane, fmaxf(__ldcs(maps_last + pixoff + 3 * plane), 0.0f));

    float acc[20];
#pragma unroll
    for (int c = 0; c < 20; c++) acc[c] = 0.f;
    const float* cb = &g_compact2[b][0][0];
#pragma unroll
    for (int k = 0; k < 16; k++) {
        float wgt = pw[k];
        const float4* row = reinterpret_cast<const float4*>(cb + po[k] * 20);
#pragma unroll
        for (int q = 0; q < 5; q++) {
            float4 v = row[q];
            acc[q * 4 + 0] += wgt * v.x;
            acc[q * 4 + 1] += wgt * v.y;
            acc[q * 4 + 2] += wgt * v.z;
            acc[q * 4 + 3] += wgt * v.w;
        }
    }
#pragma unroll
    for (int cc = 0; cc < 18; cc++) {
        int oc = (cc < 2) ? cc : cc + 2;
        __stcs(map_out + pixoff + (size_t)oc * plane,
               fmaxf(__ldcs(maps_last + pixoff + (size_t)oc * plane), acc[cc]));
    }
}

__global__ void xform_kernel(const float* __restrict__ maps_last,
                             float* __restrict__ map_out) {
    int tid = blockIdx.x * blockDim.x + threadIdx.x;
    const int WQ = MM / 4;
    if (tid >= NB * MM * WQ) return;
    int wq = tid % WQ;
    int t = tid / WQ;
    int h = t % MM;
    int b = t / MM;
    int w0 = wq * 4;

    float ct = g_pose[b][0], sn = g_pose[b][1], tx = g_pose[b][2], ty = g_pose[b][3];
    const float step = 2.0f / 479.0f;

    // Conservative window test on continuous composed back-map at strip endpoints.
    float rxmin = 1e30f, rxmax = -1e30f, rymin = 1e30f, rymax = -1e30f;
#pragma unroll
    for (int e = 0; e < 2; e++) {
        float wf = (float)(w0 + e * 3);
        float gqx = wf * step - 1.0f + tx;
        float gqy = (float)h * step - 1.0f + ty;
        float r0 = gqx * ct - gqy * sn;
        float r1 = gqx * sn + gqy * ct;
        float rx = (r0 + 1.0f) * 0.5f * 479.0f;
        float ry = (r1 + 1.0f) * 0.5f * 479.0f;
        rxmin = fminf(rxmin, rx); rxmax = fmaxf(rxmax, rx);
        rymin = fminf(rymin, ry); rymax = fmaxf(rymax, ry);
    }
    const float MG = 4.0f;
    bool maybe = (rxmax >= 190.f - MG) && (rxmin <= 289.f + MG) &&
                 (rymax >= 240.f - MG) && (rymin <= 339.f + MG);

    if (!maybe) {
        size_t plane = (size_t)MM * MM;
        size_t pixoff = (size_t)b * NC * plane + (size_t)h * MM + w0;
#pragma unroll
        for (int c = 0; c < NC; c++) {
            const float4* src = reinterpret_cast<const float4*>(maps_last + pixoff + (size_t)c * plane);
            float4 v = __ldcs(src);
            v.x = fmaxf(v.x, 0.f); v.y = fmaxf(v.y, 0.f);
            v.z = fmaxf(v.z, 0.f); v.w = fmaxf(v.w, 0.f);
            __stcs(reinterpret_cast<float4*>(map_out + pixoff + (size_t)c * plane), v);
        }
        return;
    }
#pragma unroll
    for (int e = 0; e < 4; e++)
        xform_pixel(b, h, w0 + e, maps_last, map_out, ct, sn, tx, ty);
}

// ---------------------------------------------------------------------------
extern "C" void kernel_launch(void* const* d_in, const int* in_sizes, int n_in,
                              void* d_out, int out_size) {
    const float* obs = (const float*)d_in[0];
    const float* pose_obs = (const float*)d_in[1];
    const float* maps_last = (const float*)d_in[2];
    const float* poses_last = (const float*)d_in[3];

    float* out = (float*)d_out;
    float* fp_out = out;
    float* map_out = out + (size_t)NB * VRD * VRD;
    float* poses_out = map_out + (size_t)NB * NC * MM * MM;

    float focal = (float)((NW / 2.0) / tan((79.0 / 2.0) * M_PI / 180.0));

    zero_pose_kernel<<<1024, 256>>>(pose_obs, poses_last, poses_out);
    int npix = NB * NH * NW;
    splat_kernel<<<(npix + 255) / 256, 256>>>(obs, focal);
    int nproj = NB * VRD * VRD * 4;
    proj_kernel<<<(nproj + 255) / 256, 256>>>(fp_out);
    int nx = NB * MM * (MM / 4);
    xform_kernel<<<(nx + 255) / 256, 256>>>(maps_last, map_out);
}

// round 4
// speedup vs baseline: 1.0881x; 1.0881x over previous
#include <cuda_runtime.h>
#include <math.h>

#define NB 4
#define NH 480
#define NW 640
#define NSEM 16
#define NC 20
#define MM 480
#define VRD 100
#define NZV 80
#define BANDLO 13
#define BANDN 12

// Scratch (device globals; no allocations allowed)
__device__ __align__(16) float g_vox0[NB][VRD][VRD][NZV];           // occupancy ch
__device__ __align__(16) float g_voxC[NB][VRD][VRD][BANDN][NSEM];   // sem chans, z-band only
__device__ __align__(16) float g_compact2[NB][VRD * VRD][20];       // packed: ch0,ch1,sem0..15,pad,pad
__device__ float g_pose[NB][4];                                     // cos_t, sin_t, tx, ty

__device__ __forceinline__ void red_add_v4(float* p, float a, float b, float c, float d) {
    asm volatile("red.global.add.v4.f32 [%0], {%1, %2, %3, %4};"
                 :: "l"(p), "f"(a), "f"(b), "f"(c), "f"(d) : "memory");
}
__device__ __forceinline__ void red_add_v2(float* p, float a, float b) {
    asm volatile("red.global.add.v2.f32 [%0], {%1, %2};"
                 :: "l"(p), "f"(a), "f"(b) : "memory");
}

// ---------------------------------------------------------------------------
__global__ void zero_pose_kernel(const float* __restrict__ pose_obs,
                                 const float* __restrict__ poses_last,
                                 float* __restrict__ poses_out) {
    if (blockIdx.x == 0 && threadIdx.x < NB) {
        int b = threadIdx.x;
        const float R2D = 57.29577951308232f;
        float plx = poses_last[3 * b + 0];
        float ply = poses_last[3 * b + 1];
        float plo = poses_last[3 * b + 2];
        float dx = pose_obs[3 * b + 0];
        float dy = pose_obs[3 * b + 1];
        float dth = pose_obs[3 * b + 2];
        float r = __fdiv_rn(plo, R2D);
        float sr = sinf(r), cr = cosf(r);
        float yy = __fadd_rn(__fadd_rn(ply, __fmul_rn(dx, sr)), __fmul_rn(dy, cr));
        float xx = __fsub_rn(__fadd_rn(plx, __fmul_rn(dx, cr)), __fmul_rn(dy, sr));
        float oo = __fadd_rn(plo, __fmul_rn(dth, R2D));
        oo = __fadd_rn(fmodf(__fsub_rn(oo, 180.0f), 360.0f), 180.0f);
        oo = __fsub_rn(fmodf(__fadd_rn(oo, 180.0f), 360.0f), 180.0f);
        poses_out[3 * b + 0] = xx;
        poses_out[3 * b + 1] = yy;
        poses_out[3 * b + 2] = oo;
        float stx = __fdiv_rn(-__fsub_rn(__fdiv_rn(__fmul_rn(xx, 100.0f), 5.0f), 240.0f), 240.0f);
        float sty = __fdiv_rn(-__fsub_rn(__fdiv_rn(__fmul_rn(yy, 100.0f), 5.0f), 240.0f), 240.0f);
        float tt = __fdiv_rn(__fmul_rn(__fsub_rn(90.0f, oo), 3.14159265358979323846f), 180.0f);
        g_pose[b][0] = cosf(tt);
        g_pose[b][1] = sinf(tt);
        g_pose[b][2] = stx;
        g_pose[b][3] = sty;
    }
    const int na = NB * VRD * VRD * NZV / 4;
    const int nb = NB * VRD * VRD * BANDN * NSEM / 4;
    float4* a = reinterpret_cast<float4*>(&g_vox0[0][0][0][0]);
    float4* c = reinterpret_cast<float4*>(&g_voxC[0][0][0][0][0]);
    float4 z = make_float4(0.f, 0.f, 0.f, 0.f);
    int stride = gridDim.x * blockDim.x;
    for (int i = blockIdx.x * blockDim.x + threadIdx.x; i < na; i += stride) a[i] = z;
    for (int i = blockIdx.x * blockDim.x + threadIdx.x; i < nb; i += stride) c[i] = z;
}

// ---------------------------------------------------------------------------
__global__ void splat_kernel(const float* __restrict__ obs, float focal) {
    int idx = blockIdx.x * blockDim.x + threadIdx.x;
    if (idx >= NB * NH * NW) return;
    int w = idx % NW;
    int t = idx / NW;
    int h = t % NH;
    int b = t / NH;

    size_t obs_b = (size_t)b * NC * NH * NW;
    size_t pix = (size_t)h * NW + w;
    float depth = __ldcs(obs + obs_b + (size_t)3 * NH * NW + pix);

    float X = __fdiv_rn(__fmul_rn(__fsub_rn((float)w, 319.5f), depth), focal);
    float Z = __fdiv_rn(__fmul_rn(__fsub_rn((float)(NH - 1 - h), 239.5f), depth), focal);

    float t0 = __fdiv_rn(__fadd_rn(X, 250.0f), 5.0f);
    t0 = __fmul_rn(__fdiv_rn(__fsub_rn(t0, 50.0f), 100.0f), 2.0f);
    float pos0 = __fadd_rn(__fmul_rn(t0, 50.0f), 50.0f);
    float t1 = __fdiv_rn(depth, 5.0f);
    t1 = __fmul_rn(__fdiv_rn(__fsub_rn(t1, 50.0f), 100.0f), 2.0f);
    float pos1 = __fadd_rn(__fmul_rn(t1, 50.0f), 50.0f);
    float t2 = __fdiv_rn(__fadd_rn(Z, 88.0f), 5.0f);
    t2 = __fmul_rn(__fdiv_rn(__fsub_rn(t2, 32.0f), 80.0f), 2.0f);
    float pos2 = __fadd_rn(__fmul_rn(t2, 40.0f), 40.0f);

    float f0 = floorf(pos0), f1 = floorf(pos1), f2 = floorf(pos2);
    float wg0[2], wg1[2], wg2[2];
    int i0[2], i1[2], i2[2];
#pragma unroll
    for (int o = 0; o < 2; o++) {
        float p = f0 + (float)o;
        bool s = (p > 0.0f) && (p < 100.0f);
        wg0[o] = s ? (1.0f - fabsf(__fsub_rn(pos0, p))) : 0.0f;
        i0[o] = s ? (int)p : 0;
        p = f1 + (float)o;
        s = (p > 0.0f) && (p < 100.0f);
        wg1[o] = s ? (1.0f - fabsf(__fsub_rn(pos1, p))) : 0.0f;
        i1[o] = s ? (int)p : 0;
        p = f2 + (float)o;
        s = (p > 0.0f) && (p < 80.0f);
        wg2[o] = s ? (1.0f - fabsf(__fsub_rn(pos2, p))) : 0.0f;
        i2[o] = s ? (int)p : 0;
    }
    if ((wg0[0] == 0.f && wg0[1] == 0.f) ||
        (wg1[0] == 0.f && wg1[1] == 0.f) ||
        (wg2[0] == 0.f && wg2[1] == 0.f))
        return;

    bool band = ((wg2[0] > 0.f && i2[0] >= BANDLO && i2[0] < BANDLO + BANDN) ||
                 (wg2[1] > 0.f && i2[1] >= BANDLO && i2[1] < BANDLO + BANDN));
    float sem[NSEM];
    if (band) {
#pragma unroll
        for (int s = 0; s < NSEM; s++)
            sem[s] = __ldcs(obs + obs_b + (size_t)(4 + s) * NH * NW + pix);
    }

    bool zpair = (wg2[0] > 0.f) && (wg2[1] > 0.f);
    bool zalign = zpair && ((i2[0] & 1) == 0);

#pragma unroll
    for (int a = 0; a < 2; a++) {
        if (wg0[a] == 0.f) continue;
#pragma unroll
        for (int c = 0; c < 2; c++) {
            float wac = __fmul_rn(wg0[a], wg1[c]);
            if (wac == 0.f) continue;

            float wz0 = __fmul_rn(wac, wg2[0]);
            float wz1 = __fmul_rn(wac, wg2[1]);
            float* v0base = &g_vox0[b][i1[c]][i0[a]][0];
            if (zalign) {
                red_add_v2(v0base + i2[0], wz0, wz1);
            } else {
                if (wg2[0] > 0.f) atomicAdd(v0base + i2[0], wz0);
                if (wg2[1] > 0.f) atomicAdd(v0base + i2[1], wz1);
            }

#pragma unroll
            for (int e = 0; e < 2; e++) {
                float wt = (e == 0) ? wz0 : wz1;
                if (wt == 0.f) continue;
                int zb = i2[e] - BANDLO;
                if ((unsigned)zb < (unsigned)BANDN) {
                    float* dst = &g_voxC[b][i1[c]][i0[a]][zb][0];
#pragma unroll
                    for (int q = 0; q < 4; q++)
                        red_add_v4(dst + q * 4,
                                   __fmul_rn(sem[q * 4 + 0], wt),
                                   __fmul_rn(sem[q * 4 + 1], wt),
                                   __fmul_rn(sem[q * 4 + 2], wt),
                                   __fmul_rn(sem[q * 4 + 3], wt));
                }
            }
        }
    }
}

// ---------------------------------------------------------------------------
__global__ void proj_kernel(float* __restrict__ fp_out) {
    int tid = blockIdx.x * blockDim.x + threadIdx.x;
    int cell = tid >> 2;
    int lane = tid & 3;
    if (cell >= NB * VRD * VRD) return;
    int p0 = cell % VRD;
    int t = cell / VRD;
    int p1 = t % VRD;
    int b = t / VRD;

    const float4* v0 = reinterpret_cast<const float4*>(&g_vox0[b][p1][p0][0]);
    float s_all = 0.f, s_band = 0.f;
#pragma unroll
    for (int q0 = 0; q0 < NZV / 16; q0++) {
        int q = q0 * 4 + lane;
        float4 v = __ldcs(v0 + q);
        float r0 = rintf(v.x), r1 = rintf(v.y), r2 = rintf(v.z), r3 = rintf(v.w);
        s_all += r0 + r1 + r2 + r3;
        int z = q * 4;
        if (z + 0 >= BANDLO && z + 0 < BANDLO + BANDN) s_band += r0;
        if (z + 1 >= BANDLO && z + 1 < BANDLO + BANDN) s_band += r1;
        if (z + 2 >= BANDLO && z + 2 < BANDLO + BANDN) s_band += r2;
        if (z + 3 >= BANDLO && z + 3 < BANDLO + BANDN) s_band += r3;
    }

    float ssem[NSEM];
#pragma unroll
    for (int s = 0; s < NSEM; s++) ssem[s] = 0.f;
    const float4* vc = reinterpret_cast<const float4*>(&g_voxC[b][p1][p0][0][0]);
#pragma unroll
    for (int zb0 = 0; zb0 < BANDN / 4; zb0++) {
        int zb = zb0 * 4 + lane;
#pragma unroll
        for (int q = 0; q < NSEM / 4; q++) {
            float4 v = __ldcs(vc + zb * (NSEM / 4) + q);
            ssem[q * 4 + 0] += rintf(v.x);
            ssem[q * 4 + 1] += rintf(v.y);
            ssem[q * 4 + 2] += rintf(v.z);
            ssem[q * 4 + 3] += rintf(v.w);
        }
    }

#pragma unroll
    for (int off = 1; off < 4; off <<= 1) {
        s_all += __shfl_xor_sync(0xffffffffu, s_all, off);
        s_band += __shfl_xor_sync(0xffffffffu, s_band, off);
#pragma unroll
        for (int s = 0; s < NSEM; s++)
            ssem[s] += __shfl_xor_sync(0xffffffffu, ssem[s], off);
    }

    if (lane == 0) {
        int sp = p1 * VRD + p0;
        float m = fminf(fmaxf(__fdiv_rn(s_band, 1.0f), 0.f), 1.f);
        float e = fminf(fmaxf(__fdiv_rn(s_all, 1.0f), 0.f), 1.f);
        float sv[NSEM];
#pragma unroll
        for (int s = 0; s < NSEM; s++)
            sv[s] = fminf(fmaxf(__fdiv_rn(ssem[s], 5.0f), 0.f), 1.f);
        float4* row = reinterpret_cast<float4*>(&g_compact2[b][sp][0]);
        row[0] = make_float4(m, e, sv[0], sv[1]);
        row[1] = make_float4(sv[2], sv[3], sv[4], sv[5]);
        row[2] = make_float4(sv[6], sv[7], sv[8], sv[9]);
        row[3] = make_float4(sv[10], sv[11], sv[12], sv[13]);
        row[4] = make_float4(sv[14], sv[15], 0.f, 0.f);
        fp_out[(size_t)b * VRD * VRD + sp] = m;
    }
}

// ---------------------------------------------------------------------------
// One pixel per thread. Cheap conservative box test on the continuous composed
// back-map (taps provably within 2.42 px; margin 4) routes most pixels to a
// pure copy; rare pixels do the exact two-stage 16-tap stencil.
__global__ void __launch_bounds__(256, 4)
xform_kernel(const float* __restrict__ maps_last, float* __restrict__ map_out) {
    int idx = blockIdx.x * blockDim.x + threadIdx.x;
    if (idx >= NB * MM * MM) return;
    int w = idx % MM;
    int t = idx / MM;
    int h = t % MM;
    int b = t / MM;

    float ct = g_pose[b][0], sn = g_pose[b][1], tx = g_pose[b][2], ty = g_pose[b][3];
    const float step = 2.0f / 479.0f;

    size_t plane = (size_t)MM * MM;
    size_t pixoff = (size_t)b * NC * plane + (size_t)h * MM + w;

    // conservative test in continuous composed coordinates
    {
        float gqx = (float)w * step - 1.0f + tx;
        float gqy = (float)h * step - 1.0f + ty;
        float r0 = gqx * ct - gqy * sn;
        float r1 = gqx * sn + gqy * ct;
        float rx = (r0 + 1.0f) * 0.5f * 479.0f;
        float ry = (r1 + 1.0f) * 0.5f * 479.0f;
        const float MG = 4.0f;
        bool maybe = (rx >= 190.f - MG) && (rx <= 289.f + MG) &&
                     (ry >= 240.f - MG) && (ry <= 339.f + MG);
        if (!maybe) {
#pragma unroll
            for (int c = 0; c < NC; c++)
                __stcs(map_out + pixoff + (size_t)c * plane,
                       fmaxf(__ldcs(maps_last + pixoff + (size_t)c * plane), 0.0f));
            return;
        }
    }

    // exact path
    float gx = __fsub_rn(__fmul_rn((float)w, step), 1.0f);
    float gy = __fsub_rn(__fmul_rn((float)h, step), 1.0f);
    float x = __fmul_rn(__fmul_rn(__fadd_rn(__fadd_rn(gx, tx), 1.0f), 0.5f), 479.0f);
    float y = __fmul_rn(__fmul_rn(__fadd_rn(__fadd_rn(gy, ty), 1.0f), 0.5f), 479.0f);
    float x0 = floorf(x), y0 = floorf(y);
    float wxv[2] = { __fsub_rn(__fadd_rn(x0, 1.0f), x), __fsub_rn(x, x0) };
    float wyv[2] = { __fsub_rn(__fadd_rn(y0, 1.0f), y), __fsub_rn(y, y0) };

    float pw[16];
    int po[16];
    bool any = false;
#pragma unroll
    for (int i = 0; i < 2; i++) {
        float qxf = x0 + (float)i;
#pragma unroll
        for (int j = 0; j < 2; j++) {
            float qyf = y0 + (float)j;
            float wk = __fmul_rn(wxv[i], wyv[j]);
            int base = (i * 2 + j) * 4;
            bool v = (qxf >= 0.f) && (qxf <= 479.f) && (qyf >= 0.f) && (qyf <= 479.f) && (wk > 0.f);
            float rx0 = 0.f, ry0 = 0.f;
            float wrx[2] = {0.f, 0.f}, wry[2] = {0.f, 0.f};
            if (v) {
                float gqx = __fsub_rn(__fmul_rn(qxf, step), 1.0f);
                float gqy = __fsub_rn(__fmul_rn(qyf, step), 1.0f);
                float r0 = __fsub_rn(__fmul_rn(gqx, ct), __fmul_rn(gqy, sn));
                float r1 = __fadd_rn(__fmul_rn(gqx, sn), __fmul_rn(gqy, ct));
                float rx = __fmul_rn(__fmul_rn(__fadd_rn(r0, 1.0f), 0.5f), 479.0f);
                float ry = __fmul_rn(__fmul_rn(__fadd_rn(r1, 1.0f), 0.5f), 479.0f);
                rx0 = floorf(rx);
                ry0 = floorf(ry);
                wrx[0] = __fsub_rn(__fadd_rn(rx0, 1.0f), rx);
                wrx[1] = __fsub_rn(rx, rx0);
                wry[0] = __fsub_rn(__fadd_rn(ry0, 1.0f), ry);
                wry[1] = __fsub_rn(ry, ry0);
            }
#pragma unroll
            for (int di = 0; di < 2; di++) {
#pragma unroll
                for (int dj = 0; dj < 2; dj++) {
                    float fx = rx0 + (float)di;
                    float fy = ry0 + (float)dj;
                    bool inr = v && (fx >= 190.f) && (fx <= 289.f) && (fy >= 240.f) && (fy <= 339.f);
                    float wgt = inr ? __fmul_rn(wk, __fmul_rn(wrx[di], wry[dj])) : 0.f;
                    int off = inr ? (((int)fy - 240) * VRD + ((int)fx - 190)) : 0;
                    int slot = base + di * 2 + dj;
                    pw[slot] = wgt;
                    po[slot] = off;
                    any = any || (wgt != 0.f);
                }
            }
        }
    }

    if (!any) {
#pragma unroll
        for (int c = 0; c < NC; c++)
            __stcs(map_out + pixoff + (size_t)c * plane,
                   fmaxf(__ldcs(maps_last + pixoff + (size_t)c * plane), 0.0f));
        return;
    }
    __stcs(map_out + pixoff + 2 * plane, fmaxf(__ldcs(maps_last + pixoff + 2 * plane), 0.0f));
    __stcs(map_out + pixoff + 3 * plane, fmaxf(__ldcs(maps_last + pixoff + 3 * plane), 0.0f));

    float acc[20];
#pragma unroll
    for (int c = 0; c < 20; c++) acc[c] = 0.f;
    const float* cb = &g_compact2[b][0][0];
#pragma unroll
    for (int k = 0; k < 16; k++) {
        float wgt = pw[k];
        const float4* row = reinterpret_cast<const float4*>(cb + po[k] * 20);
#pragma unroll
        for (int q = 0; q < 5; q++) {
            float4 v = row[q];
            acc[q * 4 + 0] += wgt * v.x;
            acc[q * 4 + 1] += wgt * v.y;
            acc[q * 4 + 2] += wgt * v.z;
            acc[q * 4 + 3] += wgt * v.w;
        }
    }
#pragma unroll
    for (int cc = 0; cc < 18; cc++) {
        int oc = (cc < 2) ? cc : cc + 2;
        __stcs(map_out + pixoff + (size_t)oc * plane,
               fmaxf(__ldcs(maps_last + pixoff + (size_t)oc * plane), acc[cc]));
    }
}

// ---------------------------------------------------------------------------
extern "C" void kernel_launch(void* const* d_in, const int* in_sizes, int n_in,
                              void* d_out, int out_size) {
    const float* obs = (const float*)d_in[0];
    const float* pose_obs = (const float*)d_in[1];
    const float* maps_last = (const float*)d_in[2];
    const float* poses_last = (const float*)d_in[3];

    float* out = (float*)d_out;
    float* fp_out = out;
    float* map_out = out + (size_t)NB * VRD * VRD;
    float* poses_out = map_out + (size_t)NB * NC * MM * MM;

    float focal = (float)((NW / 2.0) / tan((79.0 / 2.0) * M_PI / 180.0));

    zero_pose_kernel<<<1024, 256>>>(pose_obs, poses_last, poses_out);
    int npix = NB * NH * NW;
    splat_kernel<<<(npix + 255) / 256, 256>>>(obs, focal);
    int nproj = NB * VRD * VRD * 4;
    proj_kernel<<<(nproj + 255) / 256, 256>>>(fp_out);
    int nx = NB * MM * MM;
    xform_kernel<<<(nx + 255) / 256, 256>>>(maps_last, map_out);
}

// round 5
// speedup vs baseline: 1.3235x; 1.2163x over previous
#include <cuda_runtime.h>
#include <math.h>

#define NB 4
#define NH 480
#define NW 640
#define NSEM 16
#define NC 20
#define MM 480
#define VRD 100
#define NZV 80
#define BANDLO 13
#define BANDN 12

// Scratch (device globals; no allocations allowed)
__device__ __align__(16) float g_vox0[NB][VRD][VRD][NZV];           // occupancy ch
__device__ __align__(16) float g_voxC[NB][VRD][VRD][BANDN][NSEM];   // sem chans, z-band only
__device__ __align__(16) float g_compact2[NB][VRD * VRD][20];       // packed: ch0,ch1,sem0..15,pad,pad
__device__ float g_pose[NB][4];                                     // cos_t, sin_t, tx, ty

__device__ __forceinline__ void red_add_v4(float* p, float a, float b, float c, float d) {
    asm volatile("red.global.add.v4.f32 [%0], {%1, %2, %3, %4};"
                 :: "l"(p), "f"(a), "f"(b), "f"(c), "f"(d) : "memory");
}
__device__ __forceinline__ void red_add_v2(float* p, float a, float b) {
    asm volatile("red.global.add.v2.f32 [%0], {%1, %2};"
                 :: "l"(p), "f"(a), "f"(b) : "memory");
}

// ---------------------------------------------------------------------------
__global__ void zero_pose_kernel(const float* __restrict__ pose_obs,
                                 const float* __restrict__ poses_last,
                                 float* __restrict__ poses_out) {
    if (blockIdx.x == 0 && threadIdx.x < NB) {
        int b = threadIdx.x;
        const float R2D = 57.29577951308232f;
        float plx = poses_last[3 * b + 0];
        float ply = poses_last[3 * b + 1];
        float plo = poses_last[3 * b + 2];
        float dx = pose_obs[3 * b + 0];
        float dy = pose_obs[3 * b + 1];
        float dth = pose_obs[3 * b + 2];
        float r = __fdiv_rn(plo, R2D);
        float sr = sinf(r), cr = cosf(r);
        float yy = __fadd_rn(__fadd_rn(ply, __fmul_rn(dx, sr)), __fmul_rn(dy, cr));
        float xx = __fsub_rn(__fadd_rn(plx, __fmul_rn(dx, cr)), __fmul_rn(dy, sr));
        float oo = __fadd_rn(plo, __fmul_rn(dth, R2D));
        oo = __fadd_rn(fmodf(__fsub_rn(oo, 180.0f), 360.0f), 180.0f);
        oo = __fsub_rn(fmodf(__fadd_rn(oo, 180.0f), 360.0f), 180.0f);
        poses_out[3 * b + 0] = xx;
        poses_out[3 * b + 1] = yy;
        poses_out[3 * b + 2] = oo;
        float stx = __fdiv_rn(-__fsub_rn(__fdiv_rn(__fmul_rn(xx, 100.0f), 5.0f), 240.0f), 240.0f);
        float sty = __fdiv_rn(-__fsub_rn(__fdiv_rn(__fmul_rn(yy, 100.0f), 5.0f), 240.0f), 240.0f);
        float tt = __fdiv_rn(__fmul_rn(__fsub_rn(90.0f, oo), 3.14159265358979323846f), 180.0f);
        g_pose[b][0] = cosf(tt);
        g_pose[b][1] = sinf(tt);
        g_pose[b][2] = stx;
        g_pose[b][3] = sty;
    }
    const int na = NB * VRD * VRD * NZV / 4;
    const int nb = NB * VRD * VRD * BANDN * NSEM / 4;
    float4* a = reinterpret_cast<float4*>(&g_vox0[0][0][0][0]);
    float4* c = reinterpret_cast<float4*>(&g_voxC[0][0][0][0][0]);
    float4 z = make_float4(0.f, 0.f, 0.f, 0.f);
    int stride = gridDim.x * blockDim.x;
    for (int i = blockIdx.x * blockDim.x + threadIdx.x; i < na; i += stride) a[i] = z;
    for (int i = blockIdx.x * blockDim.x + threadIdx.x; i < nb; i += stride) c[i] = z;
}

// ---------------------------------------------------------------------------
__global__ void splat_kernel(const float* __restrict__ obs, float focal) {
    int idx = blockIdx.x * blockDim.x + threadIdx.x;
    if (idx >= NB * NH * NW) return;
    int w = idx % NW;
    int t = idx / NW;
    int h = t % NH;
    int b = t / NH;

    size_t obs_b = (size_t)b * NC * NH * NW;
    size_t pix = (size_t)h * NW + w;
    float depth = __ldcs(obs + obs_b + (size_t)3 * NH * NW + pix);

    float X = __fdiv_rn(__fmul_rn(__fsub_rn((float)w, 319.5f), depth), focal);
    float Z = __fdiv_rn(__fmul_rn(__fsub_rn((float)(NH - 1 - h), 239.5f), depth), focal);

    float t0 = __fdiv_rn(__fadd_rn(X, 250.0f), 5.0f);
    t0 = __fmul_rn(__fdiv_rn(__fsub_rn(t0, 50.0f), 100.0f), 2.0f);
    float pos0 = __fadd_rn(__fmul_rn(t0, 50.0f), 50.0f);
    float t1 = __fdiv_rn(depth, 5.0f);
    t1 = __fmul_rn(__fdiv_rn(__fsub_rn(t1, 50.0f), 100.0f), 2.0f);
    float pos1 = __fadd_rn(__fmul_rn(t1, 50.0f), 50.0f);
    float t2 = __fdiv_rn(__fadd_rn(Z, 88.0f), 5.0f);
    t2 = __fmul_rn(__fdiv_rn(__fsub_rn(t2, 32.0f), 80.0f), 2.0f);
    float pos2 = __fadd_rn(__fmul_rn(t2, 40.0f), 40.0f);

    float f0 = floorf(pos0), f1 = floorf(pos1), f2 = floorf(pos2);
    float wg0[2], wg1[2], wg2[2];
    int i0[2], i1[2], i2[2];
#pragma unroll
    for (int o = 0; o < 2; o++) {
        float p = f0 + (float)o;
        bool s = (p > 0.0f) && (p < 100.0f);
        wg0[o] = s ? (1.0f - fabsf(__fsub_rn(pos0, p))) : 0.0f;
        i0[o] = s ? (int)p : 0;
        p = f1 + (float)o;
        s = (p > 0.0f) && (p < 100.0f);
        wg1[o] = s ? (1.0f - fabsf(__fsub_rn(pos1, p))) : 0.0f;
        i1[o] = s ? (int)p : 0;
        p = f2 + (float)o;
        s = (p > 0.0f) && (p < 80.0f);
        wg2[o] = s ? (1.0f - fabsf(__fsub_rn(pos2, p))) : 0.0f;
        i2[o] = s ? (int)p : 0;
    }
    if ((wg0[0] == 0.f && wg0[1] == 0.f) ||
        (wg1[0] == 0.f && wg1[1] == 0.f) ||
        (wg2[0] == 0.f && wg2[1] == 0.f))
        return;

    bool band = ((wg2[0] > 0.f && i2[0] >= BANDLO && i2[0] < BANDLO + BANDN) ||
                 (wg2[1] > 0.f && i2[1] >= BANDLO && i2[1] < BANDLO + BANDN));
    float sem[NSEM];
    if (band) {
#pragma unroll
        for (int s = 0; s < NSEM; s++)
            sem[s] = __ldcs(obs + obs_b + (size_t)(4 + s) * NH * NW + pix);
    }

    bool zpair = (wg2[0] > 0.f) && (wg2[1] > 0.f);
    bool zalign = zpair && ((i2[0] & 1) == 0);

#pragma unroll
    for (int a = 0; a < 2; a++) {
        if (wg0[a] == 0.f) continue;
#pragma unroll
        for (int c = 0; c < 2; c++) {
            float wac = __fmul_rn(wg0[a], wg1[c]);
            if (wac == 0.f) continue;

            float wz0 = __fmul_rn(wac, wg2[0]);
            float wz1 = __fmul_rn(wac, wg2[1]);
            float* v0base = &g_vox0[b][i1[c]][i0[a]][0];
            if (zalign) {
                red_add_v2(v0base + i2[0], wz0, wz1);
            } else {
                if (wg2[0] > 0.f) atomicAdd(v0base + i2[0], wz0);
                if (wg2[1] > 0.f) atomicAdd(v0base + i2[1], wz1);
            }

#pragma unroll
            for (int e = 0; e < 2; e++) {
                float wt = (e == 0) ? wz0 : wz1;
                if (wt == 0.f) continue;
                int zb = i2[e] - BANDLO;
                if ((unsigned)zb < (unsigned)BANDN) {
                    float* dst = &g_voxC[b][i1[c]][i0[a]][zb][0];
#pragma unroll
                    for (int q = 0; q < 4; q++)
                        red_add_v4(dst + q * 4,
                                   __fmul_rn(sem[q * 4 + 0], wt),
                                   __fmul_rn(sem[q * 4 + 1], wt),
                                   __fmul_rn(sem[q * 4 + 2], wt),
                                   __fmul_rn(sem[q * 4 + 3], wt));
                }
            }
        }
    }
}

// ---------------------------------------------------------------------------
__global__ void proj_kernel(float* __restrict__ fp_out) {
    int tid = blockIdx.x * blockDim.x + threadIdx.x;
    int cell = tid >> 2;
    int lane = tid & 3;
    if (cell >= NB * VRD * VRD) return;
    int p0 = cell % VRD;
    int t = cell / VRD;
    int p1 = t % VRD;
    int b = t / VRD;

    const float4* v0 = reinterpret_cast<const float4*>(&g_vox0[b][p1][p0][0]);
    float s_all = 0.f, s_band = 0.f;
#pragma unroll
    for (int q0 = 0; q0 < NZV / 16; q0++) {
        int q = q0 * 4 + lane;
        float4 v = __ldcs(v0 + q);
        float r0 = rintf(v.x), r1 = rintf(v.y), r2 = rintf(v.z), r3 = rintf(v.w);
        s_all += r0 + r1 + r2 + r3;
        int z = q * 4;
        if (z + 0 >= BANDLO && z + 0 < BANDLO + BANDN) s_band += r0;
        if (z + 1 >= BANDLO && z + 1 < BANDLO + BANDN) s_band += r1;
        if (z + 2 >= BANDLO && z + 2 < BANDLO + BANDN) s_band += r2;
        if (z + 3 >= BANDLO && z + 3 < BANDLO + BANDN) s_band += r3;
    }

    float ssem[NSEM];
#pragma unroll
    for (int s = 0; s < NSEM; s++) ssem[s] = 0.f;
    const float4* vc = reinterpret_cast<const float4*>(&g_voxC[b][p1][p0][0][0]);
#pragma unroll
    for (int zb0 = 0; zb0 < BANDN / 4; zb0++) {
        int zb = zb0 * 4 + lane;
#pragma unroll
        for (int q = 0; q < NSEM / 4; q++) {
            float4 v = __ldcs(vc + zb * (NSEM / 4) + q);
            ssem[q * 4 + 0] += rintf(v.x);
            ssem[q * 4 + 1] += rintf(v.y);
            ssem[q * 4 + 2] += rintf(v.z);
            ssem[q * 4 + 3] += rintf(v.w);
        }
    }

#pragma unroll
    for (int off = 1; off < 4; off <<= 1) {
        s_all += __shfl_xor_sync(0xffffffffu, s_all, off);
        s_band += __shfl_xor_sync(0xffffffffu, s_band, off);
#pragma unroll
        for (int s = 0; s < NSEM; s++)
            ssem[s] += __shfl_xor_sync(0xffffffffu, ssem[s], off);
    }

    if (lane == 0) {
        int sp = p1 * VRD + p0;
        float m = fminf(fmaxf(__fdiv_rn(s_band, 1.0f), 0.f), 1.f);
        float e = fminf(fmaxf(__fdiv_rn(s_all, 1.0f), 0.f), 1.f);
        float sv[NSEM];
#pragma unroll
        for (int s = 0; s < NSEM; s++)
            sv[s] = fminf(fmaxf(__fdiv_rn(ssem[s], 5.0f), 0.f), 1.f);
        float4* row = reinterpret_cast<float4*>(&g_compact2[b][sp][0]);
        row[0] = make_float4(m, e, sv[0], sv[1]);
        row[1] = make_float4(sv[2], sv[3], sv[4], sv[5]);
        row[2] = make_float4(sv[6], sv[7], sv[8], sv[9]);
        row[3] = make_float4(sv[10], sv[11], sv[12], sv[13]);
        row[4] = make_float4(sv[14], sv[15], 0.f, 0.f);
        fp_out[(size_t)b * VRD * VRD + sp] = m;
    }
}

// ---------------------------------------------------------------------------
// Exact composed stencil for ONE pixel and ONE compact-channel. Accumulates
// directly into a scalar (no tap arrays -> low register pressure).
__device__ __forceinline__ float stencil_pixel(int w, int h, int cidx,
                                               const float* __restrict__ cb,
                                               float ct, float sn, float tx, float ty) {
    const float step = 2.0f / 479.0f;
    float gx = __fsub_rn(__fmul_rn((float)w, step), 1.0f);
    float gy = __fsub_rn(__fmul_rn((float)h, step), 1.0f);
    float x = __fmul_rn(__fmul_rn(__fadd_rn(__fadd_rn(gx, tx), 1.0f), 0.5f), 479.0f);
    float y = __fmul_rn(__fmul_rn(__fadd_rn(__fadd_rn(gy, ty), 1.0f), 0.5f), 479.0f);
    float x0 = floorf(x), y0 = floorf(y);
    float wxv[2] = { __fsub_rn(__fadd_rn(x0, 1.0f), x), __fsub_rn(x, x0) };
    float wyv[2] = { __fsub_rn(__fadd_rn(y0, 1.0f), y), __fsub_rn(y, y0) };

    float vsum = 0.f;
#pragma unroll
    for (int i = 0; i < 2; i++) {
        float qxf = x0 + (float)i;
#pragma unroll
        for (int j = 0; j < 2; j++) {
            float qyf = y0 + (float)j;
            float wk = __fmul_rn(wxv[i], wyv[j]);
            bool v = (qxf >= 0.f) && (qxf <= 479.f) && (qyf >= 0.f) && (qyf <= 479.f) && (wk > 0.f);
            if (!v) continue;
            float gqx = __fsub_rn(__fmul_rn(qxf, step), 1.0f);
            float gqy = __fsub_rn(__fmul_rn(qyf, step), 1.0f);
            float r0 = __fsub_rn(__fmul_rn(gqx, ct), __fmul_rn(gqy, sn));
            float r1 = __fadd_rn(__fmul_rn(gqx, sn), __fmul_rn(gqy, ct));
            float rx = __fmul_rn(__fmul_rn(__fadd_rn(r0, 1.0f), 0.5f), 479.0f);
            float ry = __fmul_rn(__fmul_rn(__fadd_rn(r1, 1.0f), 0.5f), 479.0f);
            float rx0 = floorf(rx);
            float ry0 = floorf(ry);
            float wrx[2] = { __fsub_rn(__fadd_rn(rx0, 1.0f), rx), __fsub_rn(rx, rx0) };
            float wry[2] = { __fsub_rn(__fadd_rn(ry0, 1.0f), ry), __fsub_rn(ry, ry0) };
#pragma unroll
            for (int di = 0; di < 2; di++) {
#pragma unroll
                for (int dj = 0; dj < 2; dj++) {
                    float fx = rx0 + (float)di;
                    float fy = ry0 + (float)dj;
                    bool inr = (fx >= 190.f) && (fx <= 289.f) && (fy >= 240.f) && (fy <= 339.f);
                    if (!inr) continue;
                    float wgt = __fmul_rn(wk, __fmul_rn(wrx[di], wry[dj]));
                    int off = ((int)fy - 240) * VRD + ((int)fx - 190);
                    vsum += wgt * cb[off * 20 + cidx];
                }
            }
        }
    }
    return vsum;
}

// One thread = (b, channel, h, 4-pixel strip). Copy path = 1 float4 ld + st.
__global__ void xform_kernel(const float* __restrict__ maps_last,
                             float* __restrict__ map_out) {
    const int WQ = MM / 4;
    int idx = blockIdx.x * blockDim.x + threadIdx.x;
    if (idx >= NB * NC * MM * WQ) return;
    int wq = idx % WQ;
    int t = idx / WQ;
    int h = t % MM;
    t = t / MM;
    int c = t % NC;
    int b = t / NC;
    int w0 = wq * 4;

    float ct = g_pose[b][0], sn = g_pose[b][1], tx = g_pose[b][2], ty = g_pose[b][3];
    const float step = 2.0f / 479.0f;

    size_t plane = (size_t)MM * MM;
    size_t off4 = (size_t)b * NC * plane + (size_t)c * plane + (size_t)h * MM + w0;
    float4 m4 = __ldcs(reinterpret_cast<const float4*>(maps_last + off4));
    m4.x = fmaxf(m4.x, 0.f); m4.y = fmaxf(m4.y, 0.f);
    m4.z = fmaxf(m4.z, 0.f); m4.w = fmaxf(m4.w, 0.f);

    // conservative strip box test (continuous composed map is linear in w)
    bool maybe;
    {
        float gqy = (float)h * step - 1.0f + ty;
        float rxa, rya, rxb, ryb;
        {
            float gqx = (float)w0 * step - 1.0f + tx;
            float r0 = gqx * ct - gqy * sn;
            float r1 = gqx * sn + gqy * ct;
            rxa = (r0 + 1.0f) * 0.5f * 479.0f;
            rya = (r1 + 1.0f) * 0.5f * 479.0f;
        }
        {
            float gqx = (float)(w0 + 3) * step - 1.0f + tx;
            float r0 = gqx * ct - gqy * sn;
            float r1 = gqx * sn + gqy * ct;
            rxb = (r0 + 1.0f) * 0.5f * 479.0f;
            ryb = (r1 + 1.0f) * 0.5f * 479.0f;
        }
        float rxmin = fminf(rxa, rxb), rxmax = fmaxf(rxa, rxb);
        float rymin = fminf(rya, ryb), rymax = fmaxf(rya, ryb);
        const float MG = 4.0f;
        maybe = (rxmax >= 190.f - MG) && (rxmin <= 289.f + MG) &&
                (rymax >= 240.f - MG) && (rymin <= 339.f + MG);
    }

    // channels 2,3 of agent_view are identically zero -> pure copy
    if (maybe && c != 2 && c != 3) {
        int cidx = (c < 2) ? c : (c - 2);
        const float* cb = &g_compact2[b][0][0];
        float v0 = stencil_pixel(w0 + 0, h, cidx, cb, ct, sn, tx, ty);
        float v1 = stencil_pixel(w0 + 1, h, cidx, cb, ct, sn, tx, ty);
        float v2 = stencil_pixel(w0 + 2, h, cidx, cb, ct, sn, tx, ty);
        float v3 = stencil_pixel(w0 + 3, h, cidx, cb, ct, sn, tx, ty);
        m4.x = fmaxf(m4.x, v0); m4.y = fmaxf(m4.y, v1);
        m4.z = fmaxf(m4.z, v2); m4.w = fmaxf(m4.w, v3);
    }
    __stcs(reinterpret_cast<float4*>(map_out + off4), m4);
}

// ---------------------------------------------------------------------------
extern "C" void kernel_launch(void* const* d_in, const int* in_sizes, int n_in,
                              void* d_out, int out_size) {
    const float* obs = (const float*)d_in[0];
    const float* pose_obs = (const float*)d_in[1];
    const float* maps_last = (const float*)d_in[2];
    const float* poses_last = (const float*)d_in[3];

    float* out = (float*)d_out;
    float* fp_out = out;
    float* map_out = out + (size_t)NB * VRD * VRD;
    float* poses_out = map_out + (size_t)NB * NC * MM * MM;

    float focal = (float)((NW / 2.0) / tan((79.0 / 2.0) * M_PI / 180.0));

    zero_pose_kernel<<<1024, 256>>>(pose_obs, poses_last, poses_out);
    int npix = NB * NH * NW;
    splat_kernel<<<(npix + 255) / 256, 256>>>(obs, focal);
    int nproj = NB * VRD * VRD * 4;
    proj_kernel<<<(nproj + 255) / 256, 256>>>(fp_out);
    int nx = NB * NC * MM * (MM / 4);
    xform_kernel<<<(nx + 255) / 256, 256>>>(maps_last, map_out);
}